// round 2
// baseline (speedup 1.0000x reference)
#include <cuda_runtime.h>
#include <cuda_bf16.h>
#include <cstdint>

#define B_ 16
#define L_ 2048
#define D_ 64
#define NE (B_*L_*D_)
#define SST 72   // smem row stride in bf16 elems (64 + 8 pad)

// bf16 hi/lo split scratch (24 MB total) — device globals, no allocation.
__device__ __nv_bfloat16 g_Qh[NE], g_Ql[NE];
__device__ __nv_bfloat16 g_Kh[NE], g_Kl[NE];
__device__ __nv_bfloat16 g_Vh[NE], g_Vl[NE];

// ---------------------------------------------------------------- K0: split
__global__ __launch_bounds__(256) void split_kernel(const float* __restrict__ src, int which, int n) {
    __nv_bfloat16 *hi, *lo;
    if (which == 0)      { hi = g_Qh; lo = g_Ql; }
    else if (which == 1) { hi = g_Kh; lo = g_Kl; }
    else                 { hi = g_Vh; lo = g_Vl; }
    int i = blockIdx.x * blockDim.x + threadIdx.x;
    if (i < n) {
        float x = src[i];
        __nv_bfloat16 h = __float2bfloat16(x);
        hi[i] = h;
        lo[i] = __float2bfloat16(x - __bfloat162float(h));
    }
}

// ------------------------------------------------------------- mma wrapper
__device__ __forceinline__ void mma_bf16(float* c,
                                         uint32_t a0, uint32_t a1, uint32_t a2, uint32_t a3,
                                         uint32_t b0, uint32_t b1) {
    asm volatile(
        "mma.sync.aligned.m16n8k16.row.col.f32.bf16.bf16.f32 "
        "{%0,%1,%2,%3}, {%4,%5,%6,%7}, {%8,%9}, {%0,%1,%2,%3};\n"
        : "+f"(c[0]), "+f"(c[1]), "+f"(c[2]), "+f"(c[3])
        : "r"(a0), "r"(a1), "r"(a2), "r"(a3), "r"(b0), "r"(b1));
}

// --------------------------------------------------- K1: S = Q K^T / 8 (fp32-accurate via bf16 split)
// grid (L/64, L/64, B), block 256. Warp layout 2(M) x 4(N), warp tile 32x16.
__global__ __launch_bounds__(256) void scores_kernel(float* __restrict__ scores) {
    __shared__ __nv_bfloat16 sQh[64*SST], sQl[64*SST], sKh[64*SST], sKl[64*SST];
    int b  = blockIdx.z;
    int m0 = blockIdx.y * 64;   // q rows
    int n0 = blockIdx.x * 64;   // k rows
    int tid = threadIdx.x;

    size_t qoff = ((size_t)b * L_ + m0) * D_;
    size_t koff = ((size_t)b * L_ + n0) * D_;
    const uint32_t* Qh32 = (const uint32_t*)(g_Qh + qoff);
    const uint32_t* Ql32 = (const uint32_t*)(g_Ql + qoff);
    const uint32_t* Kh32 = (const uint32_t*)(g_Kh + koff);
    const uint32_t* Kl32 = (const uint32_t*)(g_Kl + koff);
    #pragma unroll
    for (int it = 0; it < 8; it++) {
        int i = tid + it * 256;          // 0..2047, 32 uints per row
        int r = i >> 5, c = i & 31;
        ((uint32_t*)(sQh + r * SST))[c] = Qh32[i];
        ((uint32_t*)(sQl + r * SST))[c] = Ql32[i];
        ((uint32_t*)(sKh + r * SST))[c] = Kh32[i];
        ((uint32_t*)(sKl + r * SST))[c] = Kl32[i];
    }
    __syncthreads();

    int warp = tid >> 5, lane = tid & 31, gid = lane >> 2, tig = lane & 3;
    int wm = warp & 1, wn = warp >> 1;

    float acc[2][2][4];
    #pragma unroll
    for (int m = 0; m < 2; m++)
        #pragma unroll
        for (int j = 0; j < 2; j++)
            #pragma unroll
            for (int x = 0; x < 4; x++) acc[m][j][x] = 0.f;

    const __nv_bfloat16* Ap[3] = {sQh, sQh, sQl};
    const __nv_bfloat16* Bp[3] = {sKh, sKl, sKh};
    #pragma unroll
    for (int s = 0; s < 3; s++) {
        const __nv_bfloat16* A  = Ap[s];
        const __nv_bfloat16* Bm = Bp[s];
        #pragma unroll
        for (int kk = 0; kk < 4; kk++) {
            uint32_t a[2][4];
            #pragma unroll
            for (int m = 0; m < 2; m++) {
                int r = wm * 32 + m * 16 + gid;
                const uint32_t* p0 = (const uint32_t*)(A + r * SST + kk * 16);
                const uint32_t* p1 = (const uint32_t*)(A + (r + 8) * SST + kk * 16);
                a[m][0] = p0[tig]; a[m][2] = p0[tig + 4];
                a[m][1] = p1[tig]; a[m][3] = p1[tig + 4];
            }
            #pragma unroll
            for (int j = 0; j < 2; j++) {
                int nn = wn * 16 + j * 8 + gid;
                const uint32_t* pb = (const uint32_t*)(Bm + nn * SST + kk * 16);
                uint32_t b0 = pb[tig], b1 = pb[tig + 4];
                #pragma unroll
                for (int m = 0; m < 2; m++)
                    mma_bf16(acc[m][j], a[m][0], a[m][1], a[m][2], a[m][3], b0, b1);
            }
        }
    }
    // epilogue: scale by 1/8, write fp32 scores (attn region used as scratch)
    #pragma unroll
    for (int m = 0; m < 2; m++) {
        int r = m0 + wm * 32 + m * 16 + gid;
        #pragma unroll
        for (int j = 0; j < 2; j++) {
            int c = n0 + wn * 16 + j * 8 + tig * 2;
            *(float2*)(scores + ((size_t)b * L_ + r) * L_ + c) =
                make_float2(acc[m][j][0] * 0.125f, acc[m][j][1] * 0.125f);
            *(float2*)(scores + ((size_t)b * L_ + r + 8) * L_ + c) =
                make_float2(acc[m][j][2] * 0.125f, acc[m][j][3] * 0.125f);
        }
    }
}

// ------------------------- K2: per-row softmax -> mask -> renormalize (exact)
// grid = B*L blocks, block 256. Row (2048 fp32) staged in smem. Mask is int32.
__global__ __launch_bounds__(256) void softmax_kernel(float* __restrict__ attn,
                                                      const int* __restrict__ mask) {
    __shared__ float  row[L_];
    __shared__ float  redf[8];
    __shared__ float2 red2[8];
    int rowid = blockIdx.x;
    float* arow = attn + (size_t)rowid * L_;
    const int* mrow = mask + (size_t)rowid * L_;
    int tid = threadIdx.x, lane = tid & 31, warp = tid >> 5;
    float4* row4 = (float4*)row;

    float lmax = -3.4e38f;
    #pragma unroll
    for (int it = 0; it < 2; it++) {
        int i = tid + it * 256;
        float4 v = ((const float4*)arow)[i];
        row4[i] = v;
        lmax = fmaxf(lmax, fmaxf(fmaxf(v.x, v.y), fmaxf(v.z, v.w)));
    }
    #pragma unroll
    for (int o = 16; o; o >>= 1) lmax = fmaxf(lmax, __shfl_xor_sync(0xffffffffu, lmax, o));
    if (lane == 0) redf[warp] = lmax;
    __syncthreads();
    if (warp == 0) {
        float m = (lane < 8) ? redf[lane] : -3.4e38f;
        #pragma unroll
        for (int o = 4; o; o >>= 1) m = fmaxf(m, __shfl_xor_sync(0xffffffffu, m, o));
        if (lane == 0) redf[0] = m;
    }
    __syncthreads();
    float M = redf[0];

    const float LOG2E = 1.4426950408889634f;
    float s_u = 0.f, s_all = 0.f;
    #pragma unroll
    for (int it = 0; it < 2; it++) {
        int i = tid + it * 256;
        float4 v = row4[i];
        int4 mk = ((const int4*)mrow)[i];
        float e0 = exp2f((v.x - M) * LOG2E);
        float e1 = exp2f((v.y - M) * LOG2E);
        float e2 = exp2f((v.z - M) * LOG2E);
        float e3 = exp2f((v.w - M) * LOG2E);
        s_all += (e0 + e1) + (e2 + e3);
        if (mk.x) e0 = 0.f;
        if (mk.y) e1 = 0.f;
        if (mk.z) e2 = 0.f;
        if (mk.w) e3 = 0.f;
        s_u += (e0 + e1) + (e2 + e3);
        row4[i] = make_float4(e0, e1, e2, e3);
    }
    float2 s = make_float2(s_u, s_all);
    #pragma unroll
    for (int o = 16; o; o >>= 1) {
        s.x += __shfl_xor_sync(0xffffffffu, s.x, o);
        s.y += __shfl_xor_sync(0xffffffffu, s.y, o);
    }
    if (lane == 0) red2[warp] = s;
    __syncthreads();
    if (warp == 0) {
        float2 t = (lane < 8) ? red2[lane] : make_float2(0.f, 0.f);
        #pragma unroll
        for (int o = 4; o; o >>= 1) {
            t.x += __shfl_xor_sync(0xffffffffu, t.x, o);
            t.y += __shfl_xor_sync(0xffffffffu, t.y, o);
        }
        if (lane == 0) red2[0] = t;
    }
    __syncthreads();
    float2 T = red2[0];
    float inv = 1.f / (T.x + 1e-8f * T.y);
    #pragma unroll
    for (int it = 0; it < 2; it++) {
        int i = tid + it * 256;
        float4 v = row4[i];
        ((float4*)arow)[i] = make_float4(v.x * inv, v.y * inv, v.z * inv, v.w * inv);
    }
}

// -------------------------------- K3: O = attn @ V (bf16 split, fp32-accurate)
// grid (L/64, B), block 256. Warp layout 2(M) x 4(N), warp tile 32x16. KC=64 K-chunks.
__global__ __launch_bounds__(256) void av_kernel(const float* __restrict__ attn,
                                                 float* __restrict__ out) {
    __shared__ __nv_bfloat16 sAh[64*SST], sAl[64*SST], sVh[64*SST], sVl[64*SST];
    int b  = blockIdx.y;
    int m0 = blockIdx.x * 64;
    int tid = threadIdx.x, warp = tid >> 5, lane = tid & 31, gid = lane >> 2, tig = lane & 3;
    int wm = warp & 1, wn = warp >> 1;

    float acc[2][2][4];
    #pragma unroll
    for (int m = 0; m < 2; m++)
        #pragma unroll
        for (int j = 0; j < 2; j++)
            #pragma unroll
            for (int x = 0; x < 4; x++) acc[m][j][x] = 0.f;

    for (int k0 = 0; k0 < L_; k0 += 64) {
        // attn tile 64x64 fp32 -> split to bf16 hi/lo smem
        #pragma unroll
        for (int it = 0; it < 4; it++) {
            int i = tid + it * 256;          // 0..1023
            int r = i >> 4, c4 = i & 15;
            float4 v = *(const float4*)(attn + ((size_t)b * L_ + m0 + r) * L_ + k0 + c4 * 4);
            int o = r * SST + c4 * 4;
            __nv_bfloat16 h0 = __float2bfloat16(v.x);
            __nv_bfloat16 h1 = __float2bfloat16(v.y);
            __nv_bfloat16 h2 = __float2bfloat16(v.z);
            __nv_bfloat16 h3 = __float2bfloat16(v.w);
            sAh[o + 0] = h0; sAh[o + 1] = h1; sAh[o + 2] = h2; sAh[o + 3] = h3;
            sAl[o + 0] = __float2bfloat16(v.x - __bfloat162float(h0));
            sAl[o + 1] = __float2bfloat16(v.y - __bfloat162float(h1));
            sAl[o + 2] = __float2bfloat16(v.z - __bfloat162float(h2));
            sAl[o + 3] = __float2bfloat16(v.w - __bfloat162float(h3));
        }
        // V tile transposed into smem: sV[d][k]
        #pragma unroll
        for (int it = 0; it < 16; it++) {
            int i = tid + it * 256;          // 0..4095
            int kk = i >> 6, d = i & 63;
            size_t go = ((size_t)b * L_ + k0 + kk) * D_ + d;
            sVh[d * SST + kk] = g_Vh[go];
            sVl[d * SST + kk] = g_Vl[go];
        }
        __syncthreads();

        const __nv_bfloat16* Ap[3] = {sAh, sAh, sAl};
        const __nv_bfloat16* Bp[3] = {sVh, sVl, sVh};
        #pragma unroll
        for (int s = 0; s < 3; s++) {
            const __nv_bfloat16* A  = Ap[s];
            const __nv_bfloat16* Bm = Bp[s];
            #pragma unroll
            for (int kk = 0; kk < 4; kk++) {
                uint32_t a[2][4];
                #pragma unroll
                for (int m = 0; m < 2; m++) {
                    int r = wm * 32 + m * 16 + gid;
                    const uint32_t* p0 = (const uint32_t*)(A + r * SST + kk * 16);
                    const uint32_t* p1 = (const uint32_t*)(A + (r + 8) * SST + kk * 16);
                    a[m][0] = p0[tig]; a[m][2] = p0[tig + 4];
                    a[m][1] = p1[tig]; a[m][3] = p1[tig + 4];
                }
                #pragma unroll
                for (int j = 0; j < 2; j++) {
                    int nn = wn * 16 + j * 8 + gid;
                    const uint32_t* pb = (const uint32_t*)(Bm + nn * SST + kk * 16);
                    uint32_t b0 = pb[tig], b1 = pb[tig + 4];
                    #pragma unroll
                    for (int m = 0; m < 2; m++)
                        mma_bf16(acc[m][j], a[m][0], a[m][1], a[m][2], a[m][3], b0, b1);
                }
            }
        }
        __syncthreads();
    }
    // epilogue: out[b][row][d]
    #pragma unroll
    for (int m = 0; m < 2; m++) {
        int r = m0 + wm * 32 + m * 16 + gid;
        #pragma unroll
        for (int j = 0; j < 2; j++) {
            int c = wn * 16 + j * 8 + tig * 2;
            *(float2*)(out + ((size_t)b * L_ + r) * D_ + c) =
                make_float2(acc[m][j][0], acc[m][j][1]);
            *(float2*)(out + ((size_t)b * L_ + r + 8) * D_ + c) =
                make_float2(acc[m][j][2], acc[m][j][3]);
        }
    }
}

// ----------------------------------------------------------------- launcher
extern "C" void kernel_launch(void* const* d_in, const int* in_sizes, int n_in,
                              void* d_out, int out_size) {
    const float* q = (const float*)d_in[0];
    const float* k = (const float*)d_in[1];
    const float* v = (const float*)d_in[2];
    const int*   mask = (const int*)d_in[3];   // bool -> int32 per harness dtype contract
    float* out  = (float*)d_out;
    float* attn = out + (size_t)B_ * L_ * D_;   // attn region doubles as score scratch

    int n = NE;
    int nb = (n + 255) / 256;
    split_kernel<<<nb, 256>>>(q, 0, n);
    split_kernel<<<nb, 256>>>(k, 1, n);
    split_kernel<<<nb, 256>>>(v, 2, n);

    dim3 g1(L_ / 64, L_ / 64, B_);
    scores_kernel<<<g1, 256>>>(attn);

    softmax_kernel<<<B_ * L_, 256>>>(attn, mask);

    dim3 g3(L_ / 64, B_);
    av_kernel<<<g3, 256>>>(attn, out);
}